// round 8
// baseline (speedup 1.0000x reference)
#include <cuda_runtime.h>
#include <cuda_fp16.h>
#include <math.h>
#include <stdint.h>

#define N_ 50000
#define F_ 128
#define G_ 3
#define E_ 600000
#define NF ((size_t)N_ * F_)

// ------------------------- static device scratch -------------------------
__device__ __align__(16) float d_pre  [G_ * N_ * F_];
__device__ __align__(16) float d_conv1[G_ * N_ * F_];
__device__ __align__(16) float d_enc  [G_ * N_ * F_];
__device__ __align__(16) float d_own2 [G_ * N_ * F_];
__device__ __align__(16) float d_oth2 [G_ * N_ * F_];
__device__ __align__(16) float d_efin [G_ * N_ * F_];
__device__ __align__(16) __half d_ow1h[2 * G_ * N_ * F_];  // fp16 [own1 | oth1]
__device__ __align__(16) __half d_htmp[G_ * N_ * F_];      // fp16 gather sources
__device__ __align__(16) __half d_h6  [2 * G_ * N_ * F_];  // fp16 level-2 sources
__device__ __align__(16) __half d_hS1 [N_ * F_];           // fp16 S1
__device__ __align__(16) float d_w12  [G_ * F_ * F_];      // fc1_w @ w_conv1
__device__ __align__(16) float d_b12  [G_ * F_];           // fc1_b @ w_conv1

__device__ int   d_deg   [G_ * N_];
__device__ int   d_rowptr[G_ * (N_ + 1)];
__device__ int   d_cur   [G_ * N_];
__device__ int   d_col   [G_ * E_];
__device__ __align__(16) float d_dinv  [G_ * N_];
__device__ float d_gv    [G_ * F_];
__device__ __align__(16) float d_u     [G_ * F_];
__device__ float d_parts [16];
__device__ int   d_e64;

// ------------------------- edge dtype detection ---------------------------
__global__ void detect_dtype_k(const void* __restrict__ edges) {
    const unsigned int* w = (const unsigned int*)edges;
    __shared__ int any;
    if (threadIdx.x == 0) any = 0;
    __syncthreads();
    for (int i = threadIdx.x; i < 2048; i += blockDim.x)
        if (w[2 * i + 1] != 0u) any = 1;
    __syncthreads();
    if (threadIdx.x == 0) d_e64 = any ? 0 : 1;
}

__device__ __forceinline__ int load_edge(const void* edges, size_t idx, int e64) {
    if (e64) return (int)((const long long*)edges)[idx];
    return ((const int*)edges)[idx];
}

// ------------------------- zero + CSR build -------------------------------
__global__ void zero_k() {
    int i = blockIdx.x * blockDim.x + threadIdx.x;
    if (i < G_ * N_) d_deg[i] = 0;
    if (i < G_ * F_) d_gv[i] = 0.f;
    if (i < 16) d_parts[i] = 0.f;
}

__global__ void count_deg_k(const void* __restrict__ edges) {
    int i = blockIdx.x * blockDim.x + threadIdx.x;
    if (i >= G_ * E_) return;
    int e64 = d_e64;
    int g = i / E_, e = i - g * E_;
    int dst = load_edge(edges, (size_t)g * 2 * E_ + E_ + e, e64);
    atomicAdd(&d_deg[g * N_ + dst], 1);
}

__global__ void dinv_k() {
    int i = blockIdx.x * blockDim.x + threadIdx.x;
    if (i < G_ * N_) d_dinv[i] = rsqrtf((float)(d_deg[i] + 1));
}

// scan + write rowptr AND cur (exclusive prefix)
__global__ void scan_rowptr_k() {
    int g = blockIdx.x;
    __shared__ int sbuf[1024];
    __shared__ int soff;
    int tid = threadIdx.x;
    if (tid == 0) { soff = 0; d_rowptr[g * (N_ + 1)] = 0; }
    __syncthreads();
    for (int base = 0; base < N_; base += 1024) {
        int idx = base + tid;
        int v = (idx < N_) ? d_deg[g * N_ + idx] : 0;
        sbuf[tid] = v;
        __syncthreads();
        for (int s = 1; s < 1024; s <<= 1) {
            int t = (tid >= s) ? sbuf[tid - s] : 0;
            __syncthreads();
            sbuf[tid] += t;
            __syncthreads();
        }
        if (idx < N_) {
            int inc = soff + sbuf[tid];
            d_rowptr[g * (N_ + 1) + idx + 1] = inc;
            d_cur[g * N_ + idx] = inc - v;
        }
        __syncthreads();
        if (tid == 0) soff += sbuf[1023];
        __syncthreads();
    }
}

__global__ void fill_csr_k(const void* __restrict__ edges) {
    int i = blockIdx.x * blockDim.x + threadIdx.x;
    if (i >= G_ * E_) return;
    int e64 = d_e64;
    int g = i / E_, e = i - g * E_;
    int src = load_edge(edges, (size_t)g * 2 * E_ + e, e64);
    int dst = load_edge(edges, (size_t)g * 2 * E_ + E_ + e, e64);
    int pos = atomicAdd(&d_cur[g * N_ + dst], 1);
    d_col[(size_t)g * E_ + pos] = src;
}

// ---------------- fused weight precompute: W12 = fc1_w @ w_conv1 ----------
__global__ void fuse_w12_k(const float* __restrict__ fc1_w,
                           const float* __restrict__ fc1_b,
                           const float* __restrict__ w_conv1) {
    int g = blockIdx.x;
    int ky = blockIdx.y;          // 0..127 = W rows, 128 = bias
    int j = threadIdx.x;          // output col
    __shared__ float srow[F_];
    const float* lrow = (ky < F_) ? (fc1_w + ((size_t)g * F_ + ky) * F_) : (fc1_b + (size_t)g * F_);
    srow[j] = lrow[j];
    __syncthreads();
    float s = 0.f;
#pragma unroll 4
    for (int m = 0; m < F_; m++) s += srow[m] * w_conv1[(size_t)m * F_ + j];
    if (ky < F_) d_w12[((size_t)g * F_ + ky) * F_ + j] = s;
    else         d_b12[(size_t)g * F_ + j] = s;
}

// ------------------------- tf32 helpers ------------------------------------
__device__ __forceinline__ uint32_t f2tf32(float x) {
    uint32_t r; asm("cvt.rna.tf32.f32 %0, %1;" : "=r"(r) : "f"(x)); return r;
}

__device__ __forceinline__ void mma_tf32(float* c, const uint32_t* a,
                                         uint32_t b0, uint32_t b1) {
    asm volatile(
        "mma.sync.aligned.m16n8k8.row.col.f32.tf32.tf32.f32 "
        "{%0,%1,%2,%3}, {%4,%5,%6,%7}, {%8,%9}, {%0,%1,%2,%3};"
        : "+f"(c[0]), "+f"(c[1]), "+f"(c[2]), "+f"(c[3])
        : "r"(a[0]), "r"(a[1]), "r"(a[2]), "r"(a[3]), "r"(b0), "r"(b1));
}

#define XS_STRIDE 36
#define WS_STRIDE 136

// ------------------------- main tf32 GEMM ----------------------------------
// Y[N,128] = X@W (+X2@W2) (+bias); fp32/fp16 in, fp32/fp16 out
__global__ void __launch_bounds__(256) gemm_tf32_k(
    const void* __restrict__ Xbase, const float* __restrict__ Wbase,
    const float* __restrict__ bbase, void* __restrict__ Ybase,
    const void* __restrict__ X2base, const float* __restrict__ W2base,
    int wstride, int bstride, int half_out, int half_in)
{
    int g = blockIdx.y;
    const void* X  = half_in ? (const void*)((const __half*)Xbase + (size_t)g * NF)
                             : (const void*)((const float*)Xbase + (size_t)g * NF);
    const void* X2 = X2base ? (half_in ? (const void*)((const __half*)X2base + (size_t)g * NF)
                                       : (const void*)((const float*)X2base + (size_t)g * NF))
                            : nullptr;
    const float* W  = Wbase + (size_t)g * wstride;
    const float* bias = bbase ? (bbase + (size_t)g * bstride) : nullptr;
    int row0 = blockIdx.x * 128;

    __shared__ __align__(16) uint32_t Xs[128][XS_STRIDE];
    __shared__ __align__(16) uint32_t Ws[32][WS_STRIDE];

    int tid = threadIdx.x;
    int lane = tid & 31;
    int wid = tid >> 5;
    int wm = (wid >> 1) * 32;
    int wn = (wid & 1) * 64;

    float acc[2][8][4];
#pragma unroll
    for (int mt = 0; mt < 2; mt++)
#pragma unroll
        for (int nt = 0; nt < 8; nt++)
#pragma unroll
            for (int q = 0; q < 4; q++) acc[mt][nt][q] = 0.f;

    int nchunks = X2 ? 8 : 4;
    float4 pxv[4], pwv[4];
#define LOAD_CHUNK(ch)                                                        \
    {                                                                         \
        int k0 = ((ch) & 3) * 32;                                             \
        _Pragma("unroll")                                                     \
        for (int t = 0; t < 4; t++) {                                         \
            int idx = tid + t * 256;                                          \
            int r = idx >> 3, c = (idx & 7) * 4;                              \
            int row = row0 + r;                                               \
            pxv[t] = make_float4(0.f, 0.f, 0.f, 0.f);                         \
            if (row < N_) {                                                   \
                if (half_in) {                                                \
                    const __half* Xh = ((ch) < 4) ? (const __half*)X : (const __half*)X2; \
                    uint2 hv = *(const uint2*)(Xh + (size_t)row * 128 + k0 + c); \
                    float2 lo = __half22float2(*(__half2*)&hv.x);             \
                    float2 hi = __half22float2(*(__half2*)&hv.y);             \
                    pxv[t] = make_float4(lo.x, lo.y, hi.x, hi.y);             \
                } else {                                                      \
                    const float* Xf = ((ch) < 4) ? (const float*)X : (const float*)X2; \
                    pxv[t] = *(const float4*)(Xf + (size_t)row * 128 + k0 + c); \
                }                                                             \
            }                                                                 \
            const float* Wc = ((ch) < 4) ? W : W2base;                        \
            int k = idx >> 5, c2 = (idx & 31) * 4;                            \
            pwv[t] = *(const float4*)(Wc + (size_t)(k0 + k) * 128 + c2);      \
        }                                                                     \
    }

    LOAD_CHUNK(0);
    for (int chunk = 0; chunk < nchunks; chunk++) {
#pragma unroll
        for (int t = 0; t < 4; t++) {
            int idx = tid + t * 256;
            int r = idx >> 3, c = (idx & 7) * 4;
            uint4 u;
            u.x = f2tf32(pxv[t].x); u.y = f2tf32(pxv[t].y);
            u.z = f2tf32(pxv[t].z); u.w = f2tf32(pxv[t].w);
            *(uint4*)&Xs[r][c] = u;
            int k = idx >> 5, c2 = (idx & 31) * 4;
            uint4 w;
            w.x = f2tf32(pwv[t].x); w.y = f2tf32(pwv[t].y);
            w.z = f2tf32(pwv[t].z); w.w = f2tf32(pwv[t].w);
            *(uint4*)&Ws[k][c2] = w;
        }
        __syncthreads();
        if (chunk + 1 < nchunks) LOAD_CHUNK(chunk + 1);

#pragma unroll
        for (int kk = 0; kk < 4; kk++) {
            int kb = kk * 8;
            uint32_t a[2][4];
#pragma unroll
            for (int mt = 0; mt < 2; mt++) {
                int r = wm + mt * 16 + (lane >> 2);
                int c = kb + (lane & 3);
                a[mt][0] = Xs[r][c];
                a[mt][1] = Xs[r + 8][c];
                a[mt][2] = Xs[r][c + 4];
                a[mt][3] = Xs[r + 8][c + 4];
            }
#pragma unroll
            for (int nt = 0; nt < 8; nt++) {
                int col = wn + nt * 8 + (lane >> 2);
                uint32_t b0 = Ws[kb + (lane & 3)][col];
                uint32_t b1 = Ws[kb + (lane & 3) + 4][col];
                mma_tf32(acc[0][nt], a[0], b0, b1);
                mma_tf32(acc[1][nt], a[1], b0, b1);
            }
        }
        __syncthreads();
    }

    float* Yf = (float*)Ybase + (size_t)g * NF;
    __half* Yh = (__half*)Ybase + (size_t)g * NF;
#pragma unroll
    for (int mt = 0; mt < 2; mt++) {
        int r0 = row0 + wm + mt * 16 + (lane >> 2);
        int r1 = r0 + 8;
#pragma unroll
        for (int nt = 0; nt < 8; nt++) {
            int cb = wn + nt * 8 + 2 * (lane & 3);
            float bx = 0.f, by = 0.f;
            if (bias) { bx = bias[cb]; by = bias[cb + 1]; }
            float ox0 = acc[mt][nt][0] + bx, oy0 = acc[mt][nt][1] + by;
            float ox1 = acc[mt][nt][2] + bx, oy1 = acc[mt][nt][3] + by;
            if (half_out) {
                if (r0 < N_) *(__half2*)(Yh + (size_t)r0 * 128 + cb) = __floats2half2_rn(ox0, oy0);
                if (r1 < N_) *(__half2*)(Yh + (size_t)r1 * 128 + cb) = __floats2half2_rn(ox1, oy1);
            } else {
                if (r0 < N_) *(float2*)(Yf + (size_t)r0 * 128 + cb) = make_float2(ox0, oy0);
                if (r1 < N_) *(float2*)(Yf + (size_t)r1 * 128 + cb) = make_float2(ox1, oy1);
            }
        }
    }
}

// --------- dual-weight GEMM: pre = x@W1+b1 (fp32), htmp = x@W12+b12 (fp16) --
// block tile 64x128, 8 warps (4m x 2n), warp tile 16x64
__global__ void __launch_bounds__(256) gemm_dual_k(
    const float* __restrict__ Xall, const float* __restrict__ W1base,
    const float* __restrict__ b1base,
    float* __restrict__ Y1all, __half* __restrict__ Y2all)
{
    int g = blockIdx.y;
    const float* X = Xall + (size_t)g * NF;
    const float* W1 = W1base + (size_t)g * F_ * F_;
    const float* W2 = d_w12 + (size_t)g * F_ * F_;
    const float* b1 = b1base + (size_t)g * F_;
    const float* b2 = d_b12 + (size_t)g * F_;
    float* Y1 = Y1all + (size_t)g * NF;
    __half* Y2 = Y2all + (size_t)g * NF;
    int row0 = blockIdx.x * 64;

    __shared__ __align__(16) uint32_t Xs[64][XS_STRIDE];
    __shared__ __align__(16) uint32_t Ws1[32][WS_STRIDE];
    __shared__ __align__(16) uint32_t Ws2[32][WS_STRIDE];

    int tid = threadIdx.x;
    int lane = tid & 31;
    int wid = tid >> 5;
    int wm = (wid >> 1) * 16;
    int wn = (wid & 1) * 64;

    float acc1[8][4], acc2[8][4];
#pragma unroll
    for (int nt = 0; nt < 8; nt++)
#pragma unroll
        for (int q = 0; q < 4; q++) { acc1[nt][q] = 0.f; acc2[nt][q] = 0.f; }

    for (int chunk = 0; chunk < 4; chunk++) {
        int k0 = chunk * 32;
        // X tile 64x32 (512 float4 slots, 2 iters)
#pragma unroll
        for (int t = 0; t < 2; t++) {
            int idx = tid + t * 256;
            int r = idx >> 3, c = (idx & 7) * 4;
            int row = row0 + r;
            float4 v = make_float4(0.f, 0.f, 0.f, 0.f);
            if (row < N_) v = *(const float4*)(X + (size_t)row * 128 + k0 + c);
            uint4 u;
            u.x = f2tf32(v.x); u.y = f2tf32(v.y); u.z = f2tf32(v.z); u.w = f2tf32(v.w);
            *(uint4*)&Xs[r][c] = u;
        }
        // W tiles 32x128 each (1024 float4 slots, 4 iters)
#pragma unroll
        for (int t = 0; t < 4; t++) {
            int idx = tid + t * 256;
            int k = idx >> 5, c2 = (idx & 31) * 4;
            float4 v1 = *(const float4*)(W1 + (size_t)(k0 + k) * 128 + c2);
            float4 v2 = *(const float4*)(W2 + (size_t)(k0 + k) * 128 + c2);
            uint4 u1, u2;
            u1.x = f2tf32(v1.x); u1.y = f2tf32(v1.y); u1.z = f2tf32(v1.z); u1.w = f2tf32(v1.w);
            u2.x = f2tf32(v2.x); u2.y = f2tf32(v2.y); u2.z = f2tf32(v2.z); u2.w = f2tf32(v2.w);
            *(uint4*)&Ws1[k][c2] = u1;
            *(uint4*)&Ws2[k][c2] = u2;
        }
        __syncthreads();

#pragma unroll
        for (int kk = 0; kk < 4; kk++) {
            int kb = kk * 8;
            uint32_t a[4];
            {
                int r = wm + (lane >> 2);
                int c = kb + (lane & 3);
                a[0] = Xs[r][c];
                a[1] = Xs[r + 8][c];
                a[2] = Xs[r][c + 4];
                a[3] = Xs[r + 8][c + 4];
            }
#pragma unroll
            for (int nt = 0; nt < 8; nt++) {
                int col = wn + nt * 8 + (lane >> 2);
                uint32_t b0a = Ws1[kb + (lane & 3)][col];
                uint32_t b1a = Ws1[kb + (lane & 3) + 4][col];
                mma_tf32(acc1[nt], a, b0a, b1a);
                uint32_t b0b = Ws2[kb + (lane & 3)][col];
                uint32_t b1b = Ws2[kb + (lane & 3) + 4][col];
                mma_tf32(acc2[nt], a, b0b, b1b);
            }
        }
        __syncthreads();
    }

    int r0 = row0 + wm + (lane >> 2);
    int r1 = r0 + 8;
#pragma unroll
    for (int nt = 0; nt < 8; nt++) {
        int cb = wn + nt * 8 + 2 * (lane & 3);
        float b1x = b1[cb], b1y = b1[cb + 1];
        float b2x = b2[cb], b2y = b2[cb + 1];
        if (r0 < N_) {
            *(float2*)(Y1 + (size_t)r0 * 128 + cb) = make_float2(acc1[nt][0] + b1x, acc1[nt][1] + b1y);
            *(__half2*)(Y2 + (size_t)r0 * 128 + cb) = __floats2half2_rn(acc2[nt][0] + b2x, acc2[nt][1] + b2y);
        }
        if (r1 < N_) {
            *(float2*)(Y1 + (size_t)r1 * 128 + cb) = make_float2(acc1[nt][2] + b1x, acc1[nt][3] + b1y);
            *(__half2*)(Y2 + (size_t)r1 * 128 + cb) = __floats2half2_rn(acc2[nt][2] + b2x, acc2[nt][3] + b2y);
        }
    }
}

// ---------------- single-source GCN aggregation (+ optional gv fuse) -------
__global__ void aggh_k(const __half* __restrict__ hbase, float* __restrict__ out,
                       const float* __restrict__ bias, float* __restrict__ gv)
{
    __shared__ float sgv[F_];
    int tid = threadIdx.x;
    int warp = (blockIdx.x * blockDim.x + tid) >> 5;
    int lane = tid & 31;
    int g = blockIdx.y;
    int c0 = lane * 4;

    if (gv) {
        if (tid < F_) sgv[tid] = 0.f;
        __syncthreads();
    }

    if (warp < N_) {
        int node = warp;
        const __half* hg = hbase + (size_t)g * NF;
        const float* dv = d_dinv + g * N_;
        const int* rp = d_rowptr + g * (N_ + 1);
        const int* cg = d_col + (size_t)g * E_;

        int beg = rp[node], end = rp[node + 1];
        float4 acc = make_float4(0.f, 0.f, 0.f, 0.f);
        int e = beg;
        for (; e + 4 <= end; e += 4) {
            int s0 = cg[e], s1 = cg[e + 1], s2 = cg[e + 2], s3 = cg[e + 3];
            float w0 = dv[s0], w1 = dv[s1], w2 = dv[s2], w3 = dv[s3];
            uint2 r0 = *(const uint2*)(hg + (size_t)s0 * F_ + c0);
            uint2 r1 = *(const uint2*)(hg + (size_t)s1 * F_ + c0);
            uint2 r2 = *(const uint2*)(hg + (size_t)s2 * F_ + c0);
            uint2 r3 = *(const uint2*)(hg + (size_t)s3 * F_ + c0);
            float2 a0 = __half22float2(*(__half2*)&r0.x), b0 = __half22float2(*(__half2*)&r0.y);
            float2 a1 = __half22float2(*(__half2*)&r1.x), b1 = __half22float2(*(__half2*)&r1.y);
            float2 a2 = __half22float2(*(__half2*)&r2.x), b2 = __half22float2(*(__half2*)&r2.y);
            float2 a3 = __half22float2(*(__half2*)&r3.x), b3 = __half22float2(*(__half2*)&r3.y);
            acc.x += w0 * a0.x + w1 * a1.x + w2 * a2.x + w3 * a3.x;
            acc.y += w0 * a0.y + w1 * a1.y + w2 * a2.y + w3 * a3.y;
            acc.z += w0 * b0.x + w1 * b1.x + w2 * b2.x + w3 * b3.x;
            acc.w += w0 * b0.y + w1 * b1.y + w2 * b2.y + w3 * b3.y;
        }
        for (; e < end; e++) {
            int s = cg[e];
            float w = dv[s];
            uint2 r = *(const uint2*)(hg + (size_t)s * F_ + c0);
            float2 a = __half22float2(*(__half2*)&r.x), b = __half22float2(*(__half2*)&r.y);
            acc.x += w * a.x; acc.y += w * a.y; acc.z += w * b.x; acc.w += w * b.y;
        }
        float di = dv[node];
        float di2 = di * di;
        uint2 rs = *(const uint2*)(hg + (size_t)node * F_ + c0);
        float2 sa = __half22float2(*(__half2*)&rs.x), sb = __half22float2(*(__half2*)&rs.y);
        float4 b4 = *(const float4*)(bias + c0);
        float4 o;
        o.x = di * acc.x + di2 * sa.x + b4.x;
        o.y = di * acc.y + di2 * sa.y + b4.y;
        o.z = di * acc.z + di2 * sb.x + b4.z;
        o.w = di * acc.w + di2 * sb.y + b4.w;
        *(float4*)(out + (size_t)g * NF + (size_t)node * F_ + c0) = o;

        if (gv) {
            atomicAdd(&sgv[c0],     o.x);
            atomicAdd(&sgv[c0 + 1], o.y);
            atomicAdd(&sgv[c0 + 2], o.z);
            atomicAdd(&sgv[c0 + 3], o.w);
        }
    }

    if (gv) {
        __syncthreads();
        if (tid < F_) atomicAdd(&gv[g * F_ + tid], sgv[tid]);
    }
}

// ---------------- dual-source GCN aggregation + fused obf ------------------
__global__ void dual_agg_k(const __half* __restrict__ srcA_base,
                           const __half* __restrict__ srcB_base, int srcB_stride,
                           void* __restrict__ outA_base, void* __restrict__ outB_base,
                           const float* __restrict__ bias,
                           const float* __restrict__ cmp_base,
                           int part_base, int oth_mode, int out_half)
{
    __shared__ float sobf[8];
    int tid = threadIdx.x;
    int warp = (blockIdx.x * blockDim.x + tid) >> 5;
    int lane = tid & 31;
    int wid = tid >> 5;
    int g = blockIdx.y;
    int c0 = lane * 4;
    float obf = 0.f;

    if (warp < N_) {
        int node = warp;
        const __half* hA = srcA_base + (size_t)g * NF;
        const __half* hB = srcB_base + (size_t)g * srcB_stride;
        const float* dv = d_dinv + g * N_;
        const int* rp = d_rowptr + g * (N_ + 1);
        const int* cg = d_col + (size_t)g * E_;

        int beg = rp[node], end = rp[node + 1];
        float4 accA = make_float4(0.f, 0.f, 0.f, 0.f);
        float4 accB = make_float4(0.f, 0.f, 0.f, 0.f);
        int e = beg;
        for (; e + 2 <= end; e += 2) {
            int s0 = cg[e], s1 = cg[e + 1];
            float w0 = dv[s0], w1 = dv[s1];
            uint2 a0 = *(const uint2*)(hA + (size_t)s0 * F_ + c0);
            uint2 a1 = *(const uint2*)(hA + (size_t)s1 * F_ + c0);
            uint2 b0 = *(const uint2*)(hB + (size_t)s0 * F_ + c0);
            uint2 b1 = *(const uint2*)(hB + (size_t)s1 * F_ + c0);
            float2 ax0 = __half22float2(*(__half2*)&a0.x), az0 = __half22float2(*(__half2*)&a0.y);
            float2 ax1 = __half22float2(*(__half2*)&a1.x), az1 = __half22float2(*(__half2*)&a1.y);
            float2 bx0 = __half22float2(*(__half2*)&b0.x), bz0 = __half22float2(*(__half2*)&b0.y);
            float2 bx1 = __half22float2(*(__half2*)&b1.x), bz1 = __half22float2(*(__half2*)&b1.y);
            accA.x += w0 * ax0.x + w1 * ax1.x;  accA.y += w0 * ax0.y + w1 * ax1.y;
            accA.z += w0 * az0.x + w1 * az1.x;  accA.w += w0 * az0.y + w1 * az1.y;
            accB.x += w0 * bx0.x + w1 * bx1.x;  accB.y += w0 * bx0.y + w1 * bx1.y;
            accB.z += w0 * bz0.x + w1 * bz1.x;  accB.w += w0 * bz0.y + w1 * bz1.y;
        }
        for (; e < end; e++) {
            int s = cg[e];
            float w = dv[s];
            uint2 a = *(const uint2*)(hA + (size_t)s * F_ + c0);
            uint2 b = *(const uint2*)(hB + (size_t)s * F_ + c0);
            float2 ax = __half22float2(*(__half2*)&a.x), az = __half22float2(*(__half2*)&a.y);
            float2 bx = __half22float2(*(__half2*)&b.x), bz = __half22float2(*(__half2*)&b.y);
            accA.x += w * ax.x; accA.y += w * ax.y; accA.z += w * az.x; accA.w += w * az.y;
            accB.x += w * bx.x; accB.y += w * bx.y; accB.z += w * bz.x; accB.w += w * bz.y;
        }
        float di = dv[node];
        float di2 = di * di;
        uint2 ra = *(const uint2*)(hA + (size_t)node * F_ + c0);
        uint2 rb = *(const uint2*)(hB + (size_t)node * F_ + c0);
        float2 sax = __half22float2(*(__half2*)&ra.x), saz = __half22float2(*(__half2*)&ra.y);
        float2 sbx = __half22float2(*(__half2*)&rb.x), sbz = __half22float2(*(__half2*)&rb.y);
        float4 b4 = *(const float4*)(bias + c0);

        float4 A;
        A.x = di * accA.x + di2 * sax.x;
        A.y = di * accA.y + di2 * sax.y;
        A.z = di * accA.z + di2 * saz.x;
        A.w = di * accA.w + di2 * saz.y;
        float4 B;
        B.x = di * accB.x + di2 * sbx.x;
        B.y = di * accB.y + di2 * sbx.y;
        B.z = di * accB.z + di2 * sbz.x;
        B.w = di * accB.w + di2 * sbz.y;

        float4 oA = make_float4(A.x + b4.x, A.y + b4.y, A.z + b4.z, A.w + b4.w);
        float4 oB;
        if (oth_mode) {
            oB.x = 0.5f * (B.x - A.x) + b4.x;
            oB.y = 0.5f * (B.y - A.y) + b4.y;
            oB.z = 0.5f * (B.z - A.z) + b4.z;
            oB.w = 0.5f * (B.w - A.w) + b4.w;
        } else {
            oB = make_float4(B.x + b4.x, B.y + b4.y, B.z + b4.z, B.w + b4.w);
        }
        size_t off = (size_t)g * NF + (size_t)node * F_ + c0;
        if (out_half) {
            __half* oAp = (__half*)outA_base + off;
            __half* oBp = (__half*)outB_base + off;
            *(__half2*)oAp = __floats2half2_rn(oA.x, oA.y);
            *(__half2*)(oAp + 2) = __floats2half2_rn(oA.z, oA.w);
            *(__half2*)oBp = __floats2half2_rn(oB.x, oB.y);
            *(__half2*)(oBp + 2) = __floats2half2_rn(oB.z, oB.w);
        } else {
            *(float4*)((float*)outA_base + off) = oA;
            *(float4*)((float*)outB_base + off) = oB;
        }

        float4 cm = *(const float4*)(cmp_base + off);
        float dx = cm.x - oA.x, dy = cm.y - oA.y, dz = cm.z - oA.z, dw = cm.w - oA.w;
        obf = dx * dx + dy * dy + dz * dz + dw * dw;
    }

#pragma unroll
    for (int off = 16; off; off >>= 1) obf += __shfl_xor_sync(0xFFFFFFFFu, obf, off);
    if (lane == 0) sobf[wid] = obf;
    __syncthreads();
    if (tid == 0) {
        float s = 0.f;
#pragma unroll
        for (int w = 0; w < 8; w++) s += sobf[w];
        atomicAdd(&d_parts[part_base + g], s);
    }
}

// ------------------------- S1 = sum_g htmp_g (fp16) ------------------------
__global__ void sum3_k() {
    size_t i = (size_t)blockIdx.x * blockDim.x + threadIdx.x;
    size_t H = NF / 2;
    if (i >= H) return;
    const __half2* h = (const __half2*)d_htmp;
    float2 a = __half22float2(h[i]);
    float2 b = __half22float2(h[H + i]);
    float2 c = __half22float2(h[2 * H + i]);
    ((__half2*)d_hS1)[i] = __floats2half2_rn(a.x + b.x + c.x, a.y + b.y + c.y);
}

// ------------------------- u from gv ---------------------------------------
__global__ void compute_u_k(const float* __restrict__ att) {
    int g = blockIdx.x;
    int dcol = threadIdx.x;
    __shared__ float sv[F_];
    float m = d_gv[g * F_ + dcol] * (1.f / (float)N_);
    sv[dcol] = 1.f / (1.f + expf(-m));
    __syncthreads();
    const float* row = att + ((size_t)g * F_ + dcol) * F_;
    float s = 0.f;
#pragma unroll 4
    for (int e = 0; e < F_; e++) s += row[e] * sv[e];
    d_u[g * F_ + dcol] = s;
}

// ---------- merged: fuse_feat + used_feat + comp_re + efin obf terms -------
__global__ void fuse_comp_k(float* __restrict__ out) {
    __shared__ __align__(16) float su[G_ * F_];
    __shared__ float sred[3][8];
    int tid = threadIdx.x;
    int lane = tid & 31;
    int wid = tid >> 5;
    for (int i = tid; i < G_ * F_; i += blockDim.x) su[i] = d_u[i];
    __syncthreads();

    int node = blockIdx.x * 8 + wid;
    float l01 = 0.f, l02 = 0.f, l12 = 0.f;

    if (node < N_) {
        float4 e[G_];
#pragma unroll
        for (int j = 0; j < G_; j++)
            e[j] = *(const float4*)(d_enc + (size_t)j * NF + (size_t)node * F_ + lane * 4);
        {
            float4 o;
            float mx = (e[0].x + e[1].x + e[2].x) * (1.f / 3.f);
            float my = (e[0].y + e[1].y + e[2].y) * (1.f / 3.f);
            float mz = (e[0].z + e[1].z + e[2].z) * (1.f / 3.f);
            float mw = (e[0].w + e[1].w + e[2].w) * (1.f / 3.f);
            o.x = (mx > 0.f) ? mx : expm1f(mx);
            o.y = (my > 0.f) ? my : expm1f(my);
            o.z = (mz > 0.f) ? mz : expm1f(mz);
            o.w = (mw > 0.f) ? mw : expm1f(mw);
            *(float4*)(out + NF + (size_t)node * F_ + lane * 4) = o;
        }
        float dots[G_][G_];
#pragma unroll
        for (int i = 0; i < G_; i++) {
            float4 uu = *(const float4*)&su[i * F_ + lane * 4];
#pragma unroll
            for (int j = 0; j < G_; j++) {
                float p = e[j].x * uu.x + e[j].y * uu.y + e[j].z * uu.z + e[j].w * uu.w;
#pragma unroll
                for (int off = 16; off; off >>= 1) p += __shfl_xor_sync(0xFFFFFFFFu, p, off);
                dots[i][j] = p;
            }
        }
        if (lane == 0) {
            float* cb = out + 2 * NF;
#pragma unroll
            for (int i = 0; i < G_; i++) {
                float s[G_], tot = 0.f;
#pragma unroll
                for (int j = 0; j < G_; j++) { s[j] = 1.f / (1.f + expf(-dots[i][j])); tot += s[j]; }
                float inv = 1.f / tot;
#pragma unroll
                for (int j = 0; j < G_; j++) cb[(size_t)node * 9 + i * 3 + j] = s[j] * inv;
            }
        }
        float4 f[G_];
#pragma unroll
        for (int j = 0; j < G_; j++)
            f[j] = *(const float4*)(d_efin + (size_t)j * NF + (size_t)node * F_ + lane * 4);
        {
            float4 o;
            float mx = (f[0].x + f[1].x + f[2].x) * (1.f / 3.f);
            float my = (f[0].y + f[1].y + f[2].y) * (1.f / 3.f);
            float mz = (f[0].z + f[1].z + f[2].z) * (1.f / 3.f);
            float mw = (f[0].w + f[1].w + f[2].w) * (1.f / 3.f);
            o.x = 1.f / (1.f + expf(-mx));
            o.y = 1.f / (1.f + expf(-my));
            o.z = 1.f / (1.f + expf(-mz));
            o.w = 1.f / (1.f + expf(-mw));
            *(float4*)(out + (size_t)node * F_ + lane * 4) = o;
        }
        {
            float dx, dy, dz, dw;
            dx = f[0].x - f[1].x; dy = f[0].y - f[1].y; dz = f[0].z - f[1].z; dw = f[0].w - f[1].w;
            l01 = dx * dx + dy * dy + dz * dz + dw * dw;
            dx = f[0].x - f[2].x; dy = f[0].y - f[2].y; dz = f[0].z - f[2].z; dw = f[0].w - f[2].w;
            l02 = dx * dx + dy * dy + dz * dz + dw * dw;
            dx = f[1].x - f[2].x; dy = f[1].y - f[2].y; dz = f[1].z - f[2].z; dw = f[1].w - f[2].w;
            l12 = dx * dx + dy * dy + dz * dz + dw * dw;
        }
    }

#pragma unroll
    for (int off = 16; off; off >>= 1) {
        l01 += __shfl_xor_sync(0xFFFFFFFFu, l01, off);
        l02 += __shfl_xor_sync(0xFFFFFFFFu, l02, off);
        l12 += __shfl_xor_sync(0xFFFFFFFFu, l12, off);
    }
    if (lane == 0) { sred[0][wid] = l01; sred[1][wid] = l02; sred[2][wid] = l12; }
    __syncthreads();
    if (tid == 0) {
        float a = 0.f, b = 0.f, c = 0.f;
#pragma unroll
        for (int w = 0; w < 8; w++) { a += sred[0][w]; b += sred[1][w]; c += sred[2][w]; }
        atomicAdd(&d_parts[6], a);
        atomicAdd(&d_parts[7], b);
        atomicAdd(&d_parts[8], c);
    }
}

__global__ void finalize_k(float* __restrict__ out) {
    float obf1 = 0.f;
#pragma unroll
    for (int g = 0; g < G_; g++)
        obf1 += 0.5f * (sqrtf(d_parts[g]) + sqrtf(d_parts[3 + g]));
    float obf0 = 2.f * (sqrtf(d_parts[6]) + sqrtf(d_parts[7]) + sqrtf(d_parts[8]));
    out[2 * NF + 9 * (size_t)N_]     = obf1;
    out[2 * NF + 9 * (size_t)N_ + 1] = obf0;
}

// ------------------------- host launcher -----------------------------------
extern "C" void kernel_launch(void* const* d_in, const int* in_sizes, int n_in,
                              void* d_out, int out_size)
{
    const float* x       = (const float*)d_in[0];
    const float* fc1_w   = (const float*)d_in[1];
    const float* fc1_b   = (const float*)d_in[2];
    const float* w_conv1 = (const float*)d_in[3];
    const float* b_conv1 = (const float*)d_in[4];
    const float* w_conv2 = (const float*)d_in[5];
    const float* b_conv2 = (const float*)d_in[6];
    const float* w_dconv1 = (const float*)d_in[7];
    const float* b_dconv1 = (const float*)d_in[8];
    const float* w_dconv2 = (const float*)d_in[9];
    const float* b_dconv2 = (const float*)d_in[10];
    const float* fc2_w   = (const float*)d_in[11];
    const float* fc2_b   = (const float*)d_in[12];
    const float* att_w   = (const float*)d_in[13];
    const void*  edges   = (const void*)d_in[14];
    float* out = (float*)d_out;

    float *pre, *conv1, *enc, *own2, *oth2, *efin, *gv;
    __half *htmp, *h6, *hS1, *ow1h;
    cudaGetSymbolAddress((void**)&pre,   d_pre);
    cudaGetSymbolAddress((void**)&conv1, d_conv1);
    cudaGetSymbolAddress((void**)&enc,   d_enc);
    cudaGetSymbolAddress((void**)&own2,  d_own2);
    cudaGetSymbolAddress((void**)&oth2,  d_oth2);
    cudaGetSymbolAddress((void**)&efin,  d_efin);
    cudaGetSymbolAddress((void**)&htmp,  d_htmp);
    cudaGetSymbolAddress((void**)&h6,    d_h6);
    cudaGetSymbolAddress((void**)&hS1,   d_hS1);
    cudaGetSymbolAddress((void**)&ow1h,  d_ow1h);
    cudaGetSymbolAddress((void**)&gv,    d_gv);

    const int TB = 256;
    dim3 gemm_grid((N_ + 127) / 128, G_);
    dim3 gemm_grid6((N_ + 127) / 128, 2 * G_);
    dim3 dual_grid((N_ + 63) / 64, G_);
    dim3 agg_grid((N_ + 7) / 8, G_);
    int h2_blocks = (int)((NF / 2 + TB - 1) / TB);

    // --- CSR build ---
    detect_dtype_k<<<1, 256>>>(edges);
    zero_k<<<(G_ * N_ + TB - 1) / TB, TB>>>();
    count_deg_k<<<(G_ * E_ + TB - 1) / TB, TB>>>(edges);
    dinv_k<<<(G_ * N_ + TB - 1) / TB, TB>>>();
    scan_rowptr_k<<<G_, 1024>>>();
    fill_csr_k<<<(G_ * E_ + TB - 1) / TB, TB>>>(edges);

    // --- fused fc1/conv1 weights + dual GEMM: pre (fp32) + htmp (fp16) ---
    fuse_w12_k<<<dim3(G_, F_ + 1), F_>>>(fc1_w, fc1_b, w_conv1);
    gemm_dual_k<<<dual_grid, TB>>>(x, fc1_w, fc1_b, pre, htmp);

    // --- encoder aggs ---
    aggh_k<<<agg_grid, TB>>>(htmp, conv1, b_conv1, nullptr);
    gemm_tf32_k<<<gemm_grid, TB>>>(conv1, w_conv2, nullptr, htmp, nullptr, nullptr, 0, 0, 1, 0);
    aggh_k<<<agg_grid, TB>>>(htmp, enc, b_conv2, gv);   // enc + fused gv reduction
    compute_u_k<<<G_, F_>>>(att_w);

    // --- decoder ---
    gemm_tf32_k<<<gemm_grid, TB>>>(enc, w_dconv1, nullptr, htmp, nullptr, nullptr, 0, 0, 1, 0); // t1
    sum3_k<<<h2_blocks, TB>>>();                                                                // S1
    dual_agg_k<<<agg_grid, TB>>>(htmp, hS1, 0, ow1h, ow1h + G_ * NF, b_dconv1, conv1, 3, 1, 1);
    gemm_tf32_k<<<gemm_grid6, TB>>>(ow1h, w_dconv2, nullptr, h6, nullptr, nullptr, 0, 0, 1, 1);
    dual_agg_k<<<agg_grid, TB>>>(h6, h6 + G_ * NF, NF, own2, oth2, b_dconv2, pre, 0, 0, 0);

    // --- each_fin = [own2, oth2] @ fc2_w + fc2_b ---
    gemm_tf32_k<<<gemm_grid, TB>>>(own2, fc2_w, fc2_b, efin, oth2, fc2_w + F_ * F_, 0, 0, 0, 0);

    // --- outputs ---
    fuse_comp_k<<<(N_ + 7) / 8, TB>>>(out);
    finalize_k<<<1, 1>>>(out);
}

// round 9
// speedup vs baseline: 1.1432x; 1.1432x over previous
#include <cuda_runtime.h>
#include <cuda_fp16.h>
#include <math.h>
#include <stdint.h>

#define N_ 50000
#define F_ 128
#define G_ 3
#define E_ 600000
#define NF ((size_t)N_ * F_)
#define SB_ 49   // scan blocks per graph (49*1024 >= 50000)

// ------------------------- static device scratch -------------------------
__device__ __align__(16) float d_pre  [G_ * N_ * F_];
__device__ __align__(16) float d_conv1[G_ * N_ * F_];
__device__ __align__(16) float d_enc  [G_ * N_ * F_];
__device__ __align__(16) float d_own2 [G_ * N_ * F_];
__device__ __align__(16) float d_oth2 [G_ * N_ * F_];
__device__ __align__(16) float d_ow1  [2 * G_ * N_ * F_];  // [own1 g0..2 | oth1 g0..2]
__device__ __align__(16) float d_efin [G_ * N_ * F_];
__device__ __align__(16) __half d_htmp[G_ * N_ * F_];      // fp16 gather sources
__device__ __align__(16) __half d_h6  [2 * G_ * N_ * F_];  // fp16 level-2 sources
__device__ __align__(16) __half d_hS1 [N_ * F_];           // fp16 S1 = sum_g enc_g@W1

__device__ int   d_deg   [G_ * N_];
__device__ int   d_rowptr[G_ * (N_ + 1)];
__device__ int   d_cur   [G_ * N_];
__device__ int   d_col   [G_ * E_];
__device__ int   d_bsum  [G_ * SB_];
__device__ __align__(16) float d_dinv  [G_ * N_];
__device__ float d_gv    [G_ * F_];
__device__ __align__(16) float d_u     [G_ * F_];
__device__ float d_parts [16];
__device__ int   d_e64;

// ------------------------- edge dtype detection ---------------------------
__global__ void detect_dtype_k(const void* __restrict__ edges) {
    const unsigned int* w = (const unsigned int*)edges;
    __shared__ int any;
    if (threadIdx.x == 0) any = 0;
    __syncthreads();
    for (int i = threadIdx.x; i < 2048; i += blockDim.x)
        if (w[2 * i + 1] != 0u) any = 1;
    __syncthreads();
    if (threadIdx.x == 0) d_e64 = any ? 0 : 1;
}

__device__ __forceinline__ int load_edge(const void* edges, size_t idx, int e64) {
    if (e64) return (int)((const long long*)edges)[idx];
    return ((const int*)edges)[idx];
}

// ------------------------- zero + CSR build -------------------------------
__global__ void zero_k() {
    int i = blockIdx.x * blockDim.x + threadIdx.x;
    if (i < G_ * N_) d_deg[i] = 0;
    if (i < G_ * F_) d_gv[i] = 0.f;
    if (i < 16) d_parts[i] = 0.f;
}

__global__ void count_deg_k(const void* __restrict__ edges) {
    int i = blockIdx.x * blockDim.x + threadIdx.x;
    if (i >= G_ * E_) return;
    int e64 = d_e64;
    int g = i / E_, e = i - g * E_;
    int dst = load_edge(edges, (size_t)g * 2 * E_ + E_ + e, e64);
    atomicAdd(&d_deg[g * N_ + dst], 1);
}

// --- 3-phase multi-block prefix scan over degrees (+ dinv + cur fused) ---
__global__ void scan_p1_k() {          // grid (SB_, G_), 256 threads
    int g = blockIdx.y, b = blockIdx.x;
    int tid = threadIdx.x;
    int base = b * 1024 + tid * 4;
    int v = 0;
#pragma unroll
    for (int j = 0; j < 4; j++) {
        int idx = base + j;
        if (idx < N_) v += d_deg[g * N_ + idx];
    }
    __shared__ int red[256];
    red[tid] = v;
    __syncthreads();
    for (int s = 128; s > 0; s >>= 1) {
        if (tid < s) red[tid] += red[tid + s];
        __syncthreads();
    }
    if (tid == 0) d_bsum[g * SB_ + b] = red[0];
}

__global__ void scan_p2_k() {          // grid G_, 32 threads
    int g = blockIdx.x;
    if (threadIdx.x == 0) {
        int acc = 0;
        for (int b = 0; b < SB_; b++) {
            int t = d_bsum[g * SB_ + b];
            d_bsum[g * SB_ + b] = acc;   // exclusive block offsets
            acc += t;
        }
    }
}

__global__ void scan_p3_k() {          // grid (SB_, G_), 256 threads
    int g = blockIdx.y, b = blockIdx.x;
    int tid = threadIdx.x;
    int base = b * 1024 + tid * 4;
    int v[4]; int s = 0;
#pragma unroll
    for (int j = 0; j < 4; j++) {
        int idx = base + j;
        v[j] = (idx < N_) ? d_deg[g * N_ + idx] : 0;
        s += v[j];
    }
    __shared__ int sc[256];
    sc[tid] = s;
    __syncthreads();
    for (int st = 1; st < 256; st <<= 1) {
        int t = (tid >= st) ? sc[tid - st] : 0;
        __syncthreads();
        sc[tid] += t;
        __syncthreads();
    }
    int run = d_bsum[g * SB_ + b] + sc[tid] - s;   // exclusive prefix
    if (b == 0 && tid == 0) d_rowptr[g * (N_ + 1)] = 0;
#pragma unroll
    for (int j = 0; j < 4; j++) {
        int idx = base + j;
        if (idx < N_) {
            d_cur[g * N_ + idx] = run;
            run += v[j];
            d_rowptr[g * (N_ + 1) + idx + 1] = run;
            d_dinv[g * N_ + idx] = rsqrtf((float)(v[j] + 1));
        }
    }
}

__global__ void fill_csr_k(const void* __restrict__ edges) {
    int i = blockIdx.x * blockDim.x + threadIdx.x;
    if (i >= G_ * E_) return;
    int e64 = d_e64;
    int g = i / E_, e = i - g * E_;
    int src = load_edge(edges, (size_t)g * 2 * E_ + e, e64);
    int dst = load_edge(edges, (size_t)g * 2 * E_ + E_ + e, e64);
    int pos = atomicAdd(&d_cur[g * N_ + dst], 1);
    d_col[(size_t)g * E_ + pos] = src;
}

// ------------------------- tf32 tensor-core GEMM --------------------------
__device__ __forceinline__ uint32_t f2tf32(float x) {
    uint32_t r; asm("cvt.rna.tf32.f32 %0, %1;" : "=r"(r) : "f"(x)); return r;
}

__device__ __forceinline__ void mma_tf32(float* c, const uint32_t* a,
                                         uint32_t b0, uint32_t b1) {
    asm volatile(
        "mma.sync.aligned.m16n8k8.row.col.f32.tf32.tf32.f32 "
        "{%0,%1,%2,%3}, {%4,%5,%6,%7}, {%8,%9}, {%0,%1,%2,%3};"
        : "+f"(c[0]), "+f"(c[1]), "+f"(c[2]), "+f"(c[3])
        : "r"(a[0]), "r"(a[1]), "r"(a[2]), "r"(a[3]), "r"(b0), "r"(b1));
}

#define XS_STRIDE 36
#define WS_STRIDE 136

__global__ void __launch_bounds__(256) gemm_tf32_k(
    const float* __restrict__ Xbase, const float* __restrict__ Wbase,
    const float* __restrict__ bbase, void* __restrict__ Ybase,
    const float* __restrict__ X2base, const float* __restrict__ W2base,
    int wstride, int bstride, int half_out)
{
    int g = blockIdx.y;
    const float* X  = Xbase + (size_t)g * NF;
    const float* W  = Wbase + (size_t)g * wstride;
    const float* X2 = X2base ? (X2base + (size_t)g * NF) : nullptr;
    const float* bias = bbase ? (bbase + (size_t)g * bstride) : nullptr;
    int row0 = blockIdx.x * 128;

    __shared__ __align__(16) uint32_t Xs[128][XS_STRIDE];
    __shared__ __align__(16) uint32_t Ws[32][WS_STRIDE];

    int tid = threadIdx.x;
    int lane = tid & 31;
    int wid = tid >> 5;
    int wm = (wid >> 1) * 32;
    int wn = (wid & 1) * 64;

    float acc[2][8][4];
#pragma unroll
    for (int mt = 0; mt < 2; mt++)
#pragma unroll
        for (int nt = 0; nt < 8; nt++)
#pragma unroll
            for (int q = 0; q < 4; q++) acc[mt][nt][q] = 0.f;

    int nchunks = X2 ? 8 : 4;

    float4 pxv[4], pwv[4];
#define LOAD_CHUNK(ch)                                                        \
    {                                                                         \
        const float* Xc = ((ch) < 4) ? X : X2;                                \
        const float* Wc = ((ch) < 4) ? W : W2base;                            \
        int k0 = ((ch) & 3) * 32;                                             \
        _Pragma("unroll")                                                     \
        for (int t = 0; t < 4; t++) {                                         \
            int idx = tid + t * 256;                                          \
            int r = idx >> 3, c = (idx & 7) * 4;                              \
            int row = row0 + r;                                               \
            pxv[t] = make_float4(0.f, 0.f, 0.f, 0.f);                         \
            if (row < N_) pxv[t] = *(const float4*)(Xc + (size_t)row * 128 + k0 + c); \
            int k = idx >> 5, c2 = (idx & 31) * 4;                            \
            pwv[t] = *(const float4*)(Wc + (size_t)(k0 + k) * 128 + c2);      \
        }                                                                     \
    }

    LOAD_CHUNK(0);
    for (int chunk = 0; chunk < nchunks; chunk++) {
#pragma unroll
        for (int t = 0; t < 4; t++) {
            int idx = tid + t * 256;
            int r = idx >> 3, c = (idx & 7) * 4;
            uint4 u;
            u.x = f2tf32(pxv[t].x); u.y = f2tf32(pxv[t].y);
            u.z = f2tf32(pxv[t].z); u.w = f2tf32(pxv[t].w);
            *(uint4*)&Xs[r][c] = u;
            int k = idx >> 5, c2 = (idx & 31) * 4;
            uint4 w;
            w.x = f2tf32(pwv[t].x); w.y = f2tf32(pwv[t].y);
            w.z = f2tf32(pwv[t].z); w.w = f2tf32(pwv[t].w);
            *(uint4*)&Ws[k][c2] = w;
        }
        __syncthreads();
        if (chunk + 1 < nchunks) LOAD_CHUNK(chunk + 1);

#pragma unroll
        for (int kk = 0; kk < 4; kk++) {
            int kb = kk * 8;
            uint32_t a[2][4];
#pragma unroll
            for (int mt = 0; mt < 2; mt++) {
                int r = wm + mt * 16 + (lane >> 2);
                int c = kb + (lane & 3);
                a[mt][0] = Xs[r][c];
                a[mt][1] = Xs[r + 8][c];
                a[mt][2] = Xs[r][c + 4];
                a[mt][3] = Xs[r + 8][c + 4];
            }
#pragma unroll
            for (int nt = 0; nt < 8; nt++) {
                int col = wn + nt * 8 + (lane >> 2);
                uint32_t b0 = Ws[kb + (lane & 3)][col];
                uint32_t b1 = Ws[kb + (lane & 3) + 4][col];
                mma_tf32(acc[0][nt], a[0], b0, b1);
                mma_tf32(acc[1][nt], a[1], b0, b1);
            }
        }
        __syncthreads();
    }

    float* Yf = (float*)Ybase + (size_t)g * NF;
    __half* Yh = (__half*)Ybase + (size_t)g * NF;
#pragma unroll
    for (int mt = 0; mt < 2; mt++) {
        int r0 = row0 + wm + mt * 16 + (lane >> 2);
        int r1 = r0 + 8;
#pragma unroll
        for (int nt = 0; nt < 8; nt++) {
            int cb = wn + nt * 8 + 2 * (lane & 3);
            float bx = 0.f, by = 0.f;
            if (bias) { bx = bias[cb]; by = bias[cb + 1]; }
            float ox0 = acc[mt][nt][0] + bx, oy0 = acc[mt][nt][1] + by;
            float ox1 = acc[mt][nt][2] + bx, oy1 = acc[mt][nt][3] + by;
            if (half_out) {
                if (r0 < N_) *(__half2*)(Yh + (size_t)r0 * 128 + cb) = __floats2half2_rn(ox0, oy0);
                if (r1 < N_) *(__half2*)(Yh + (size_t)r1 * 128 + cb) = __floats2half2_rn(ox1, oy1);
            } else {
                if (r0 < N_) *(float2*)(Yf + (size_t)r0 * 128 + cb) = make_float2(ox0, oy0);
                if (r1 < N_) *(float2*)(Yf + (size_t)r1 * 128 + cb) = make_float2(ox1, oy1);
            }
        }
    }
}

// ---------------- single-source GCN aggregation (encoder) -----------------
__global__ void aggh_k(const __half* __restrict__ hbase, float* __restrict__ out,
                       const float* __restrict__ bias)
{
    int warp = (blockIdx.x * blockDim.x + threadIdx.x) >> 5;
    int lane = threadIdx.x & 31;
    if (warp >= N_) return;
    int g = blockIdx.y;
    int node = warp;
    int c0 = lane * 4;

    const __half* hg = hbase + (size_t)g * NF;
    const float* dv = d_dinv + g * N_;
    const int* rp = d_rowptr + g * (N_ + 1);
    const int* cg = d_col + (size_t)g * E_;

    int beg = rp[node], end = rp[node + 1];
    float4 acc = make_float4(0.f, 0.f, 0.f, 0.f);
    int e = beg;
    for (; e + 4 <= end; e += 4) {
        int s0 = cg[e], s1 = cg[e + 1], s2 = cg[e + 2], s3 = cg[e + 3];
        float w0 = dv[s0], w1 = dv[s1], w2 = dv[s2], w3 = dv[s3];
        uint2 r0 = *(const uint2*)(hg + (size_t)s0 * F_ + c0);
        uint2 r1 = *(const uint2*)(hg + (size_t)s1 * F_ + c0);
        uint2 r2 = *(const uint2*)(hg + (size_t)s2 * F_ + c0);
        uint2 r3 = *(const uint2*)(hg + (size_t)s3 * F_ + c0);
        float2 a0 = __half22float2(*(__half2*)&r0.x), b0 = __half22float2(*(__half2*)&r0.y);
        float2 a1 = __half22float2(*(__half2*)&r1.x), b1 = __half22float2(*(__half2*)&r1.y);
        float2 a2 = __half22float2(*(__half2*)&r2.x), b2 = __half22float2(*(__half2*)&r2.y);
        float2 a3 = __half22float2(*(__half2*)&r3.x), b3 = __half22float2(*(__half2*)&r3.y);
        acc.x += w0 * a0.x + w1 * a1.x + w2 * a2.x + w3 * a3.x;
        acc.y += w0 * a0.y + w1 * a1.y + w2 * a2.y + w3 * a3.y;
        acc.z += w0 * b0.x + w1 * b1.x + w2 * b2.x + w3 * b3.x;
        acc.w += w0 * b0.y + w1 * b1.y + w2 * b2.y + w3 * b3.y;
    }
    for (; e < end; e++) {
        int s = cg[e];
        float w = dv[s];
        uint2 r = *(const uint2*)(hg + (size_t)s * F_ + c0);
        float2 a = __half22float2(*(__half2*)&r.x), b = __half22float2(*(__half2*)&r.y);
        acc.x += w * a.x; acc.y += w * a.y; acc.z += w * b.x; acc.w += w * b.y;
    }
    float di = dv[node];
    float di2 = di * di;
    uint2 rs = *(const uint2*)(hg + (size_t)node * F_ + c0);
    float2 sa = __half22float2(*(__half2*)&rs.x), sb = __half22float2(*(__half2*)&rs.y);
    float4 b4 = *(const float4*)(bias + c0);
    float4 o;
    o.x = di * acc.x + di2 * sa.x + b4.x;
    o.y = di * acc.y + di2 * sa.y + b4.y;
    o.z = di * acc.z + di2 * sb.x + b4.z;
    o.w = di * acc.w + di2 * sb.y + b4.w;
    *(float4*)(out + (size_t)g * NF + (size_t)node * F_ + c0) = o;
}

// ---------------- dual-source GCN aggregation + fused obf ------------------
__global__ void dual_agg_k(const __half* __restrict__ srcA_base,
                           const __half* __restrict__ srcB_base, int srcB_stride,
                           float* __restrict__ outA_base, float* __restrict__ outB_base,
                           const float* __restrict__ bias,
                           const float* __restrict__ cmp_base,
                           int part_base, int oth_mode)
{
    __shared__ float sobf[8];
    int tid = threadIdx.x;
    int warp = (blockIdx.x * blockDim.x + tid) >> 5;
    int lane = tid & 31;
    int wid = tid >> 5;
    int g = blockIdx.y;
    int c0 = lane * 4;
    float obf = 0.f;

    if (warp < N_) {
        int node = warp;
        const __half* hA = srcA_base + (size_t)g * NF;
        const __half* hB = srcB_base + (size_t)g * srcB_stride;
        const float* dv = d_dinv + g * N_;
        const int* rp = d_rowptr + g * (N_ + 1);
        const int* cg = d_col + (size_t)g * E_;

        int beg = rp[node], end = rp[node + 1];
        float4 accA = make_float4(0.f, 0.f, 0.f, 0.f);
        float4 accB = make_float4(0.f, 0.f, 0.f, 0.f);
        int e = beg;
        for (; e + 2 <= end; e += 2) {
            int s0 = cg[e], s1 = cg[e + 1];
            float w0 = dv[s0], w1 = dv[s1];
            uint2 a0 = *(const uint2*)(hA + (size_t)s0 * F_ + c0);
            uint2 a1 = *(const uint2*)(hA + (size_t)s1 * F_ + c0);
            uint2 b0 = *(const uint2*)(hB + (size_t)s0 * F_ + c0);
            uint2 b1 = *(const uint2*)(hB + (size_t)s1 * F_ + c0);
            float2 ax0 = __half22float2(*(__half2*)&a0.x), az0 = __half22float2(*(__half2*)&a0.y);
            float2 ax1 = __half22float2(*(__half2*)&a1.x), az1 = __half22float2(*(__half2*)&a1.y);
            float2 bx0 = __half22float2(*(__half2*)&b0.x), bz0 = __half22float2(*(__half2*)&b0.y);
            float2 bx1 = __half22float2(*(__half2*)&b1.x), bz1 = __half22float2(*(__half2*)&b1.y);
            accA.x += w0 * ax0.x + w1 * ax1.x;  accA.y += w0 * ax0.y + w1 * ax1.y;
            accA.z += w0 * az0.x + w1 * az1.x;  accA.w += w0 * az0.y + w1 * az1.y;
            accB.x += w0 * bx0.x + w1 * bx1.x;  accB.y += w0 * bx0.y + w1 * bx1.y;
            accB.z += w0 * bz0.x + w1 * bz1.x;  accB.w += w0 * bz0.y + w1 * bz1.y;
        }
        for (; e < end; e++) {
            int s = cg[e];
            float w = dv[s];
            uint2 a = *(const uint2*)(hA + (size_t)s * F_ + c0);
            uint2 b = *(const uint2*)(hB + (size_t)s * F_ + c0);
            float2 ax = __half22float2(*(__half2*)&a.x), az = __half22float2(*(__half2*)&a.y);
            float2 bx = __half22float2(*(__half2*)&b.x), bz = __half22float2(*(__half2*)&b.y);
            accA.x += w * ax.x; accA.y += w * ax.y; accA.z += w * az.x; accA.w += w * az.y;
            accB.x += w * bx.x; accB.y += w * bx.y; accB.z += w * bz.x; accB.w += w * bz.y;
        }
        float di = dv[node];
        float di2 = di * di;
        uint2 ra = *(const uint2*)(hA + (size_t)node * F_ + c0);
        uint2 rb = *(const uint2*)(hB + (size_t)node * F_ + c0);
        float2 sax = __half22float2(*(__half2*)&ra.x), saz = __half22float2(*(__half2*)&ra.y);
        float2 sbx = __half22float2(*(__half2*)&rb.x), sbz = __half22float2(*(__half2*)&rb.y);
        float4 b4 = *(const float4*)(bias + c0);

        float4 A;
        A.x = di * accA.x + di2 * sax.x;
        A.y = di * accA.y + di2 * sax.y;
        A.z = di * accA.z + di2 * saz.x;
        A.w = di * accA.w + di2 * saz.y;
        float4 B;
        B.x = di * accB.x + di2 * sbx.x;
        B.y = di * accB.y + di2 * sbx.y;
        B.z = di * accB.z + di2 * sbz.x;
        B.w = di * accB.w + di2 * sbz.y;

        float4 oA = make_float4(A.x + b4.x, A.y + b4.y, A.z + b4.z, A.w + b4.w);
        float4 oB;
        if (oth_mode) {
            oB.x = 0.5f * (B.x - A.x) + b4.x;
            oB.y = 0.5f * (B.y - A.y) + b4.y;
            oB.z = 0.5f * (B.z - A.z) + b4.z;
            oB.w = 0.5f * (B.w - A.w) + b4.w;
        } else {
            oB = make_float4(B.x + b4.x, B.y + b4.y, B.z + b4.z, B.w + b4.w);
        }
        size_t off = (size_t)g * NF + (size_t)node * F_ + c0;
        *(float4*)(outA_base + off) = oA;
        *(float4*)(outB_base + off) = oB;

        float4 cm = *(const float4*)(cmp_base + off);
        float dx = cm.x - oA.x, dy = cm.y - oA.y, dz = cm.z - oA.z, dw = cm.w - oA.w;
        obf = dx * dx + dy * dy + dz * dz + dw * dw;
    }

#pragma unroll
    for (int off = 16; off; off >>= 1) obf += __shfl_xor_sync(0xFFFFFFFFu, obf, off);
    if (lane == 0) sobf[wid] = obf;
    __syncthreads();
    if (tid == 0) {
        float s = 0.f;
#pragma unroll
        for (int w = 0; w < 8; w++) s += sobf[w];
        atomicAdd(&d_parts[part_base + g], s);
    }
}

// ------------------------- S1 = sum_g htmp_g (fp16) ------------------------
__global__ void sum3_k() {
    size_t i = (size_t)blockIdx.x * blockDim.x + threadIdx.x;
    size_t H = NF / 2;
    if (i >= H) return;
    const __half2* h = (const __half2*)d_htmp;
    float2 a = __half22float2(h[i]);
    float2 b = __half22float2(h[H + i]);
    float2 c = __half22float2(h[2 * H + i]);
    ((__half2*)d_hS1)[i] = __floats2half2_rn(a.x + b.x + c.x, a.y + b.y + c.y);
}

// ------------------------- global_vec + u ---------------------------------
__global__ void gv_reduce_k() {
    int g = blockIdx.y;
    int f = threadIdx.x;
    int n0 = blockIdx.x * 512;
    int nend = n0 + 512; if (nend > N_) nend = N_;
    float s = 0.f;
    const float* eg = d_enc + (size_t)g * NF;
    for (int n = n0; n < nend; n++) s += eg[(size_t)n * F_ + f];
    atomicAdd(&d_gv[g * F_ + f], s);
}

__global__ void compute_u_k(const float* __restrict__ att) {
    int g = blockIdx.x;
    int dcol = threadIdx.x;
    __shared__ float sv[F_];
    float m = d_gv[g * F_ + dcol] * (1.f / (float)N_);
    sv[dcol] = 1.f / (1.f + expf(-m));
    __syncthreads();
    const float* row = att + ((size_t)g * F_ + dcol) * F_;
    float s = 0.f;
#pragma unroll 4
    for (int e = 0; e < F_; e++) s += row[e] * sv[e];
    d_u[g * F_ + dcol] = s;
}

// ---------- merged: fuse_feat + used_feat + comp_re + efin obf terms -------
__global__ void fuse_comp_k(float* __restrict__ out) {
    __shared__ __align__(16) float su[G_ * F_];
    __shared__ float sred[3][8];
    int tid = threadIdx.x;
    int lane = tid & 31;
    int wid = tid >> 5;
    for (int i = tid; i < G_ * F_; i += blockDim.x) su[i] = d_u[i];
    __syncthreads();

    int node = blockIdx.x * 8 + wid;
    float l01 = 0.f, l02 = 0.f, l12 = 0.f;

    if (node < N_) {
        float4 e[G_];
#pragma unroll
        for (int j = 0; j < G_; j++)
            e[j] = *(const float4*)(d_enc + (size_t)j * NF + (size_t)node * F_ + lane * 4);
        {
            float4 o;
            float mx = (e[0].x + e[1].x + e[2].x) * (1.f / 3.f);
            float my = (e[0].y + e[1].y + e[2].y) * (1.f / 3.f);
            float mz = (e[0].z + e[1].z + e[2].z) * (1.f / 3.f);
            float mw = (e[0].w + e[1].w + e[2].w) * (1.f / 3.f);
            o.x = (mx > 0.f) ? mx : expm1f(mx);
            o.y = (my > 0.f) ? my : expm1f(my);
            o.z = (mz > 0.f) ? mz : expm1f(mz);
            o.w = (mw > 0.f) ? mw : expm1f(mw);
            *(float4*)(out + NF + (size_t)node * F_ + lane * 4) = o;
        }
        float dots[G_][G_];
#pragma unroll
        for (int i = 0; i < G_; i++) {
            float4 uu = *(const float4*)&su[i * F_ + lane * 4];
#pragma unroll
            for (int j = 0; j < G_; j++) {
                float p = e[j].x * uu.x + e[j].y * uu.y + e[j].z * uu.z + e[j].w * uu.w;
#pragma unroll
                for (int off = 16; off; off >>= 1) p += __shfl_xor_sync(0xFFFFFFFFu, p, off);
                dots[i][j] = p;
            }
        }
        if (lane == 0) {
            float* cb = out + 2 * NF;
#pragma unroll
            for (int i = 0; i < G_; i++) {
                float s[G_], tot = 0.f;
#pragma unroll
                for (int j = 0; j < G_; j++) { s[j] = 1.f / (1.f + expf(-dots[i][j])); tot += s[j]; }
                float inv = 1.f / tot;
#pragma unroll
                for (int j = 0; j < G_; j++) cb[(size_t)node * 9 + i * 3 + j] = s[j] * inv;
            }
        }
        float4 f[G_];
#pragma unroll
        for (int j = 0; j < G_; j++)
            f[j] = *(const float4*)(d_efin + (size_t)j * NF + (size_t)node * F_ + lane * 4);
        {
            float4 o;
            float mx = (f[0].x + f[1].x + f[2].x) * (1.f / 3.f);
            float my = (f[0].y + f[1].y + f[2].y) * (1.f / 3.f);
            float mz = (f[0].z + f[1].z + f[2].z) * (1.f / 3.f);
            float mw = (f[0].w + f[1].w + f[2].w) * (1.f / 3.f);
            o.x = 1.f / (1.f + expf(-mx));
            o.y = 1.f / (1.f + expf(-my));
            o.z = 1.f / (1.f + expf(-mz));
            o.w = 1.f / (1.f + expf(-mw));
            *(float4*)(out + (size_t)node * F_ + lane * 4) = o;
        }
        {
            float dx, dy, dz, dw;
            dx = f[0].x - f[1].x; dy = f[0].y - f[1].y; dz = f[0].z - f[1].z; dw = f[0].w - f[1].w;
            l01 = dx * dx + dy * dy + dz * dz + dw * dw;
            dx = f[0].x - f[2].x; dy = f[0].y - f[2].y; dz = f[0].z - f[2].z; dw = f[0].w - f[2].w;
            l02 = dx * dx + dy * dy + dz * dz + dw * dw;
            dx = f[1].x - f[2].x; dy = f[1].y - f[2].y; dz = f[1].z - f[2].z; dw = f[1].w - f[2].w;
            l12 = dx * dx + dy * dy + dz * dz + dw * dw;
        }
    }

#pragma unroll
    for (int off = 16; off; off >>= 1) {
        l01 += __shfl_xor_sync(0xFFFFFFFFu, l01, off);
        l02 += __shfl_xor_sync(0xFFFFFFFFu, l02, off);
        l12 += __shfl_xor_sync(0xFFFFFFFFu, l12, off);
    }
    if (lane == 0) { sred[0][wid] = l01; sred[1][wid] = l02; sred[2][wid] = l12; }
    __syncthreads();
    if (tid == 0) {
        float a = 0.f, b = 0.f, c = 0.f;
#pragma unroll
        for (int w = 0; w < 8; w++) { a += sred[0][w]; b += sred[1][w]; c += sred[2][w]; }
        atomicAdd(&d_parts[6], a);
        atomicAdd(&d_parts[7], b);
        atomicAdd(&d_parts[8], c);
    }
}

__global__ void finalize_k(float* __restrict__ out) {
    float obf1 = 0.f;
#pragma unroll
    for (int g = 0; g < G_; g++)
        obf1 += 0.5f * (sqrtf(d_parts[g]) + sqrtf(d_parts[3 + g]));
    float obf0 = 2.f * (sqrtf(d_parts[6]) + sqrtf(d_parts[7]) + sqrtf(d_parts[8]));
    out[2 * NF + 9 * (size_t)N_]     = obf1;
    out[2 * NF + 9 * (size_t)N_ + 1] = obf0;
}

// ------------------------- host launcher -----------------------------------
extern "C" void kernel_launch(void* const* d_in, const int* in_sizes, int n_in,
                              void* d_out, int out_size)
{
    const float* x       = (const float*)d_in[0];
    const float* fc1_w   = (const float*)d_in[1];
    const float* fc1_b   = (const float*)d_in[2];
    const float* w_conv1 = (const float*)d_in[3];
    const float* b_conv1 = (const float*)d_in[4];
    const float* w_conv2 = (const float*)d_in[5];
    const float* b_conv2 = (const float*)d_in[6];
    const float* w_dconv1 = (const float*)d_in[7];
    const float* b_dconv1 = (const float*)d_in[8];
    const float* w_dconv2 = (const float*)d_in[9];
    const float* b_dconv2 = (const float*)d_in[10];
    const float* fc2_w   = (const float*)d_in[11];
    const float* fc2_b   = (const float*)d_in[12];
    const float* att_w   = (const float*)d_in[13];
    const void*  edges   = (const void*)d_in[14];
    float* out = (float*)d_out;

    float *pre, *conv1, *enc, *own2, *oth2, *ow1, *efin;
    __half *htmp, *h6, *hS1;
    cudaGetSymbolAddress((void**)&pre,   d_pre);
    cudaGetSymbolAddress((void**)&conv1, d_conv1);
    cudaGetSymbolAddress((void**)&enc,   d_enc);
    cudaGetSymbolAddress((void**)&own2,  d_own2);
    cudaGetSymbolAddress((void**)&oth2,  d_oth2);
    cudaGetSymbolAddress((void**)&ow1,   d_ow1);
    cudaGetSymbolAddress((void**)&efin,  d_efin);
    cudaGetSymbolAddress((void**)&htmp,  d_htmp);
    cudaGetSymbolAddress((void**)&h6,    d_h6);
    cudaGetSymbolAddress((void**)&hS1,   d_hS1);

    const int TB = 256;
    dim3 gemm_grid((N_ + 127) / 128, G_);
    dim3 gemm_grid6((N_ + 127) / 128, 2 * G_);
    dim3 agg_grid((N_ + 7) / 8, G_);
    dim3 scan_grid(SB_, G_);
    int h2_blocks = (int)((NF / 2 + TB - 1) / TB);

    // --- edge dtype detection + CSR build (multi-block scan) ---
    detect_dtype_k<<<1, 256>>>(edges);
    zero_k<<<(G_ * N_ + TB - 1) / TB, TB>>>();
    count_deg_k<<<(G_ * E_ + TB - 1) / TB, TB>>>(edges);
    scan_p1_k<<<scan_grid, TB>>>();
    scan_p2_k<<<G_, 32>>>();
    scan_p3_k<<<scan_grid, TB>>>();
    fill_csr_k<<<(G_ * E_ + TB - 1) / TB, TB>>>(edges);

    // --- encoder ---
    gemm_tf32_k<<<gemm_grid, TB>>>(x, fc1_w, fc1_b, pre, nullptr, nullptr, F_ * F_, F_, 0);
    gemm_tf32_k<<<gemm_grid, TB>>>(pre, w_conv1, nullptr, htmp, nullptr, nullptr, 0, 0, 1);
    aggh_k<<<agg_grid, TB>>>(htmp, conv1, b_conv1);
    gemm_tf32_k<<<gemm_grid, TB>>>(conv1, w_conv2, nullptr, htmp, nullptr, nullptr, 0, 0, 1);
    aggh_k<<<agg_grid, TB>>>(htmp, enc, b_conv2);

    // --- global vec + attention u ---
    gv_reduce_k<<<dim3((N_ + 511) / 512, G_), F_>>>();
    compute_u_k<<<G_, F_>>>(att_w);

    // --- decoder ---
    gemm_tf32_k<<<gemm_grid, TB>>>(enc, w_dconv1, nullptr, htmp, nullptr, nullptr, 0, 0, 1); // t1
    sum3_k<<<h2_blocks, TB>>>();                                                             // S1
    dual_agg_k<<<agg_grid, TB>>>(htmp, hS1, 0, ow1, ow1 + G_ * NF, b_dconv1, conv1, 3, 1);
    gemm_tf32_k<<<gemm_grid6, TB>>>(ow1, w_dconv2, nullptr, h6, nullptr, nullptr, 0, 0, 1);
    dual_agg_k<<<agg_grid, TB>>>(h6, h6 + G_ * NF, NF, own2, oth2, b_dconv2, pre, 0, 0);

    // --- each_fin = [own2, oth2] @ fc2_w + fc2_b (single fused K=256 GEMM) ---
    gemm_tf32_k<<<gemm_grid, TB>>>(own2, fc2_w, fc2_b, efin, oth2, fc2_w + F_ * F_, 0, 0, 0);

    // --- outputs ---
    fuse_comp_k<<<(N_ + 7) / 8, TB>>>(out);
    finalize_k<<<1, 1>>>(out);
}